// round 11
// baseline (speedup 1.0000x reference)
#include <cuda_runtime.h>
#include <cuda_bf16.h>
#include <math_constants.h>

#define BS 16
#define NQ 900
#define NC 91
#define NT 1600
#define NR (BS * NQ)
#define TQ 8            // queries per block
#define TT 320          // targets per chunk (160 threads x 2)
#define NCHUNK (NT / TT)

// ---------------------------------------------------------------------------
// Packed f32x2 helpers (SASS FADD2/FMUL2/FFMA2 — PTX-only on Blackwell)
// ---------------------------------------------------------------------------
union F2 {
    unsigned long long u;
    float2 f;
};
__device__ __forceinline__ F2 mkf2(float lo, float hi) {
    F2 r; r.f.x = lo; r.f.y = hi; return r;
}
__device__ __forceinline__ F2 add2(F2 a, F2 b) {
    F2 r; asm("add.rn.f32x2 %0, %1, %2;" : "=l"(r.u) : "l"(a.u), "l"(b.u)); return r;
}
__device__ __forceinline__ F2 mul2(F2 a, F2 b) {
    F2 r; asm("mul.rn.f32x2 %0, %1, %2;" : "=l"(r.u) : "l"(a.u), "l"(b.u)); return r;
}
__device__ __forceinline__ F2 fma2(F2 a, F2 b, F2 c) {
    F2 r; asm("fma.rn.f32x2 %0, %1, %2, %3;" : "=l"(r.u) : "l"(a.u), "l"(b.u), "l"(c.u)); return r;
}
__device__ __forceinline__ float rcpa(float x) {
    float r; asm("rcp.approx.f32 %0, %1;" : "=f"(r) : "f"(x)); return r;
}

// ---------------------------------------------------------------------------
// Single fused kernel. grid = NR/TQ = 1800 blocks, 160 threads.
// Block owns TQ=8 query rows and ALL 1600 targets (5 chunks of 320):
//  - prologue: softmax of the 8 rows (computed exactly ONCE chip-wide),
//    stored to smem as (2 - p)
//  - mainloop: min/max-free cost math, identical to the validated R8 loop.
//
// Per axis: dh=qh-th, dl=ql-tl, D=|dh|+|dl|, fx=dh-dl,
//   base = qw+tw;  2w = base-D (clamp 0);  2dx = base+D
// uni4 = 4(qa+ta) - inter'   (inter'=4*inter, ac'=4*ac)
// C = 2.5(|ex|+|ey|) + 5(|fx|+|fy|) + (2-p) - 2*(inter'*ac' + uni4^2)*rcp(uni4*ac')
// ---------------------------------------------------------------------------
struct __align__(16) QEntry {
    float4 a;   // qlx,qlx,qhx,qhx
    float4 b;   // qly,qly,qhy,qhy
    float2 c;   // 4*qa, 4*qa
};
union Q4 { float4 v; F2 h[2]; };
union Q2 { float2 v; F2 h; };

__global__ void __launch_bounds__(160) fused_cost_kernel(
    const float* __restrict__ pred_logits,
    const float* __restrict__ pred_boxes,
    const float* __restrict__ tgt_bbox,
    const int*   __restrict__ tgt_ids,
    float*       __restrict__ out)
{
    __shared__ QEntry sq[TQ];
    __shared__ float  sprob[TQ * NC];   // (2 - softmax) for this block's rows

    const int tid   = threadIdx.x;
    const int wid   = tid >> 5;
    const int lane  = tid & 31;
    const int qbase = blockIdx.x * TQ;

    if (tid < TQ) {
        float4 b = reinterpret_cast<const float4*>(pred_boxes)[qbase + tid];
        float lx = b.x - 0.5f * b.z, hx = b.x + 0.5f * b.z;
        float ly = b.y - 0.5f * b.w, hy = b.y + 0.5f * b.w;
        float a4 = 4.0f * b.z * b.w;
        sq[tid].a = make_float4(lx, lx, hx, hx);
        sq[tid].b = make_float4(ly, ly, hy, hy);
        sq[tid].c = make_float2(a4, a4);
    }

    // Softmax of this block's TQ rows: 5 warps cover 8 rows (warp w: w, w+5).
    // No max-subtraction (logits O(1), exp can't overflow; tol 1e-3).
    for (int r = wid; r < TQ; r += 5) {
        const float* in = pred_logits + (size_t)(qbase + r) * NC;
        float v0 = in[lane];
        float v1 = in[lane + 32];
        bool has2 = (lane + 64 < NC);
        float v2 = has2 ? in[lane + 64] : 0.0f;

        float e0 = __expf(v0);
        float e1 = __expf(v1);
        float e2 = has2 ? __expf(v2) : 0.0f;
        float s = e0 + e1 + e2;
        #pragma unroll
        for (int o = 16; o; o >>= 1) s += __shfl_xor_sync(0xffffffffu, s, o);

        float inv = rcpa(s);
        float* dst = sprob + r * NC;
        dst[lane]      = fmaf(-e0, inv, 2.0f);
        dst[lane + 32] = fmaf(-e1, inv, 2.0f);
        if (has2) dst[lane + 64] = fmaf(-e2, inv, 2.0f);
    }

    const F2 CM1 = mkf2(-1.0f, -1.0f);
    const F2 CM2 = mkf2(-2.0f, -2.0f);

    float* opb = out + (size_t)qbase * NT;

    __syncthreads();

    #pragma unroll 1
    for (int c = 0; c < NCHUNK; c++) {
        const int j0 = c * TT + 2 * tid;
        const int j1 = j0 + 1;

        float4 tc0 = reinterpret_cast<const float4*>(tgt_bbox)[j0];
        float4 tc1 = reinterpret_cast<const float4*>(tgt_bbox)[j1];
        const int id0 = tgt_ids[j0];
        const int id1 = tgt_ids[j1];

        // packed pre-negated target corners: -th, -tl per axis
        F2 nthx = mkf2(-fmaf(0.5f, tc0.z,  tc0.x), -fmaf(0.5f, tc1.z,  tc1.x));
        F2 ntlx = mkf2( fmaf(0.5f, tc0.z, -tc0.x),  fmaf(0.5f, tc1.z, -tc1.x));
        F2 nthy = mkf2(-fmaf(0.5f, tc0.w,  tc0.y), -fmaf(0.5f, tc1.w,  tc1.y));
        F2 ntly = mkf2( fmaf(0.5f, tc0.w, -tc0.y),  fmaf(0.5f, tc1.w, -tc1.y));
        F2 tw2x = mkf2(2.0f * tc0.z, 2.0f * tc1.z);
        F2 tw2y = mkf2(2.0f * tc0.w, 2.0f * tc1.w);
        F2 ta4  = mkf2(4.0f * tc0.z * tc0.w, 4.0f * tc1.z * tc1.w);

        // Front-batch prob gathers: 16 independent LDS (MLP=16, one exposure)
        float pa[TQ], pb[TQ];
        #pragma unroll
        for (int qi = 0; qi < TQ; qi++) {
            pa[qi] = sprob[qi * NC + id0];
            pb[qi] = sprob[qi * NC + id1];
        }

        #pragma unroll
        for (int qi = 0; qi < TQ; qi++) {
            Q4 A; A.v = sq[qi].a;            // LDS.128 broadcast
            Q4 B; B.v = sq[qi].b;            // LDS.128 broadcast
            Q2 Cq; Cq.v = sq[qi].c;          // LDS.64  broadcast
            F2 qlx2 = A.h[0], qhx2 = A.h[1];
            F2 qly2 = B.h[0], qhy2 = B.h[1];
            F2 qa4  = Cq.h;

            // axis deltas
            F2 dhx = add2(qhx2, nthx);
            F2 dlx = add2(qlx2, ntlx);
            F2 dhy = add2(qhy2, nthy);
            F2 dly = add2(qly2, ntly);
            F2 fx  = fma2(dlx, CM1, dhx);    // dh - dl = qw - tw
            F2 fy  = fma2(dly, CM1, dhy);

            F2 Dx = mkf2(fabsf(dhx.f.x) + fabsf(dlx.f.x),
                         fabsf(dhx.f.y) + fabsf(dlx.f.y));
            F2 Dy = mkf2(fabsf(dhy.f.x) + fabsf(dly.f.x),
                         fabsf(dhy.f.y) + fabsf(dly.f.y));

            F2 bx = add2(fx, tw2x);          // qw + tw
            F2 by = add2(fy, tw2y);
            F2 ux = fma2(Dx, CM1, bx);       // 2*w (unclamped)
            F2 uy = fma2(Dy, CM1, by);
            F2 vx = add2(bx, Dx);            // 2*dx enclosing
            F2 vy = add2(by, Dy);

            F2 uxc = mkf2(fmaxf(ux.f.x, 0.0f), fmaxf(ux.f.y, 0.0f));
            F2 uyc = mkf2(fmaxf(uy.f.x, 0.0f), fmaxf(uy.f.y, 0.0f));

            F2 inter2 = mul2(uxc, uyc);          // 4*inter
            F2 sum4   = add2(qa4, ta4);          // 4*(qa+ta)
            F2 uni4   = fma2(inter2, CM1, sum4); // 4*uni
            F2 ac2    = mul2(vx, vy);            // 4*ac
            F2 prod2  = mul2(uni4, ac2);         // 16*uni*ac
            F2 r2     = mkf2(rcpa(prod2.f.x), rcpa(prod2.f.y));
            F2 iac2   = mul2(inter2, ac2);
            F2 S2     = fma2(uni4, uni4, iac2);  // 16*(inter*ac + uni^2)
            F2 mr2    = mul2(r2, CM2);           // -2/(16*uni*ac)

            // L1 cost pieces (pa/pb already hold 2-p)
            F2 ex = add2(dhx, dlx);              // 2*(qc - tc)
            F2 ey = add2(dhy, dly);
            float t0 = fmaf(fabsf(ex.f.x) + fabsf(ey.f.x), 2.5f,
                       fmaf(fabsf(fx.f.x) + fabsf(fy.f.x), 5.0f, pa[qi]));
            float t1 = fmaf(fabsf(ex.f.y) + fabsf(ey.f.y), 2.5f,
                       fmaf(fabsf(fx.f.y) + fabsf(fy.f.y), 5.0f, pb[qi]));

            F2 C2 = fma2(S2, mr2, mkf2(t0, t1));

            *reinterpret_cast<float2*>(opb + qi * NT + j0) = C2.f;
        }
    }
}

// ---------------------------------------------------------------------------
extern "C" void kernel_launch(void* const* d_in, const int* in_sizes, int n_in,
                              void* d_out, int out_size)
{
    const float* pred_logits = (const float*)d_in[0];
    const float* pred_boxes  = (const float*)d_in[1];
    const float* tgt_bbox    = (const float*)d_in[2];
    const int*   tgt_ids     = (const int*)d_in[3];
    float* out = (float*)d_out;

    fused_cost_kernel<<<NR / TQ, 160>>>(pred_logits, pred_boxes,
                                        tgt_bbox, tgt_ids, out);
}

// round 12
// speedup vs baseline: 1.1597x; 1.1597x over previous
#include <cuda_runtime.h>
#include <cuda_bf16.h>
#include <math_constants.h>

#define BS 16
#define NQ 900
#define NC 91
#define NT 1600
#define NR (BS * NQ)
#define TQ 8            // queries per block
#define TT 320          // targets per chunk (160 threads x 2)
#define NCHUNK (NT / TT)

// ---------------------------------------------------------------------------
// Packed f32x2 helpers (SASS FADD2/FMUL2/FFMA2 — PTX-only on Blackwell)
// ---------------------------------------------------------------------------
union F2 {
    unsigned long long u;
    float2 f;
};
__device__ __forceinline__ F2 mkf2(float lo, float hi) {
    F2 r; r.f.x = lo; r.f.y = hi; return r;
}
__device__ __forceinline__ F2 add2(F2 a, F2 b) {
    F2 r; asm("add.rn.f32x2 %0, %1, %2;" : "=l"(r.u) : "l"(a.u), "l"(b.u)); return r;
}
__device__ __forceinline__ F2 mul2(F2 a, F2 b) {
    F2 r; asm("mul.rn.f32x2 %0, %1, %2;" : "=l"(r.u) : "l"(a.u), "l"(b.u)); return r;
}
__device__ __forceinline__ F2 fma2(F2 a, F2 b, F2 c) {
    F2 r; asm("fma.rn.f32x2 %0, %1, %2, %3;" : "=l"(r.u) : "l"(a.u), "l"(b.u), "l"(c.u)); return r;
}
__device__ __forceinline__ float rcpa(float x) {
    float r; asm("rcp.approx.f32 %0, %1;" : "=f"(r) : "f"(x)); return r;
}

// ---------------------------------------------------------------------------
// Single fused kernel. grid = NR/TQ = 1800 blocks, 160 threads,
// __launch_bounds__(160, 6): cap regs at ~68 (R11's uncapped build chose 128
// regs -> occ 20% -> latency-hiding collapse; R8's best mainloop ran at 51
// regs / 47% occ, which 6 blocks/SM reproduces).
//
// Block owns TQ=8 query rows and ALL 1600 targets (5 chunks of 320):
//  - prologue: softmax of the 8 rows (computed exactly ONCE chip-wide),
//    stored to smem as (2 - p)
//  - mainloop: min/max-free cost math, identical to the validated R8 loop.
//
// Per axis: dh=qh-th, dl=ql-tl, D=|dh|+|dl|, fx=dh-dl,
//   base = qw+tw;  2w = base-D (clamp 0);  2dx = base+D
// uni4 = 4(qa+ta) - inter'   (inter'=4*inter, ac'=4*ac)
// C = 2.5(|ex|+|ey|) + 5(|fx|+|fy|) + (2-p) - 2*(inter'*ac' + uni4^2)*rcp(uni4*ac')
// ---------------------------------------------------------------------------
struct __align__(16) QEntry {
    float4 a;   // qlx,qlx,qhx,qhx
    float4 b;   // qly,qly,qhy,qhy
    float2 c;   // 4*qa, 4*qa
};
union Q4 { float4 v; F2 h[2]; };
union Q2 { float2 v; F2 h; };

__global__ void __launch_bounds__(160, 6) fused_cost_kernel(
    const float* __restrict__ pred_logits,
    const float* __restrict__ pred_boxes,
    const float* __restrict__ tgt_bbox,
    const int*   __restrict__ tgt_ids,
    float*       __restrict__ out)
{
    __shared__ QEntry sq[TQ];
    __shared__ float  sprob[TQ * NC];   // (2 - softmax) for this block's rows

    const int tid   = threadIdx.x;
    const int wid   = tid >> 5;
    const int lane  = tid & 31;
    const int qbase = blockIdx.x * TQ;

    if (tid < TQ) {
        float4 b = reinterpret_cast<const float4*>(pred_boxes)[qbase + tid];
        float lx = b.x - 0.5f * b.z, hx = b.x + 0.5f * b.z;
        float ly = b.y - 0.5f * b.w, hy = b.y + 0.5f * b.w;
        float a4 = 4.0f * b.z * b.w;
        sq[tid].a = make_float4(lx, lx, hx, hx);
        sq[tid].b = make_float4(ly, ly, hy, hy);
        sq[tid].c = make_float2(a4, a4);
    }

    // Softmax of this block's TQ rows: 5 warps cover 8 rows (warp w: w, w+5).
    // No max-subtraction (logits O(1), exp can't overflow; tol 1e-3).
    for (int r = wid; r < TQ; r += 5) {
        const float* in = pred_logits + (size_t)(qbase + r) * NC;
        float v0 = in[lane];
        float v1 = in[lane + 32];
        bool has2 = (lane + 64 < NC);
        float v2 = has2 ? in[lane + 64] : 0.0f;

        float e0 = __expf(v0);
        float e1 = __expf(v1);
        float e2 = has2 ? __expf(v2) : 0.0f;
        float s = e0 + e1 + e2;
        #pragma unroll
        for (int o = 16; o; o >>= 1) s += __shfl_xor_sync(0xffffffffu, s, o);

        float inv = rcpa(s);
        float* dst = sprob + r * NC;
        dst[lane]      = fmaf(-e0, inv, 2.0f);
        dst[lane + 32] = fmaf(-e1, inv, 2.0f);
        if (has2) dst[lane + 64] = fmaf(-e2, inv, 2.0f);
    }

    const F2 CM1 = mkf2(-1.0f, -1.0f);
    const F2 CM2 = mkf2(-2.0f, -2.0f);

    float* opb = out + (size_t)qbase * NT;

    __syncthreads();

    #pragma unroll 1
    for (int c = 0; c < NCHUNK; c++) {
        const int j0 = c * TT + 2 * tid;
        const int j1 = j0 + 1;

        float4 tc0 = reinterpret_cast<const float4*>(tgt_bbox)[j0];
        float4 tc1 = reinterpret_cast<const float4*>(tgt_bbox)[j1];
        const int id0 = tgt_ids[j0];
        const int id1 = tgt_ids[j1];

        // packed pre-negated target corners: -th, -tl per axis
        F2 nthx = mkf2(-fmaf(0.5f, tc0.z,  tc0.x), -fmaf(0.5f, tc1.z,  tc1.x));
        F2 ntlx = mkf2( fmaf(0.5f, tc0.z, -tc0.x),  fmaf(0.5f, tc1.z, -tc1.x));
        F2 nthy = mkf2(-fmaf(0.5f, tc0.w,  tc0.y), -fmaf(0.5f, tc1.w,  tc1.y));
        F2 ntly = mkf2( fmaf(0.5f, tc0.w, -tc0.y),  fmaf(0.5f, tc1.w, -tc1.y));
        F2 tw2x = mkf2(2.0f * tc0.z, 2.0f * tc1.z);
        F2 tw2y = mkf2(2.0f * tc0.w, 2.0f * tc1.w);
        F2 ta4  = mkf2(4.0f * tc0.z * tc0.w, 4.0f * tc1.z * tc1.w);

        // Front-batch prob gathers: 16 independent LDS (MLP=16, one exposure)
        float pa[TQ], pb[TQ];
        #pragma unroll
        for (int qi = 0; qi < TQ; qi++) {
            pa[qi] = sprob[qi * NC + id0];
            pb[qi] = sprob[qi * NC + id1];
        }

        #pragma unroll
        for (int qi = 0; qi < TQ; qi++) {
            Q4 A; A.v = sq[qi].a;            // LDS.128 broadcast
            Q4 B; B.v = sq[qi].b;            // LDS.128 broadcast
            Q2 Cq; Cq.v = sq[qi].c;          // LDS.64  broadcast
            F2 qlx2 = A.h[0], qhx2 = A.h[1];
            F2 qly2 = B.h[0], qhy2 = B.h[1];
            F2 qa4  = Cq.h;

            // axis deltas
            F2 dhx = add2(qhx2, nthx);
            F2 dlx = add2(qlx2, ntlx);
            F2 dhy = add2(qhy2, nthy);
            F2 dly = add2(qly2, ntly);
            F2 fx  = fma2(dlx, CM1, dhx);    // dh - dl = qw - tw
            F2 fy  = fma2(dly, CM1, dhy);

            F2 Dx = mkf2(fabsf(dhx.f.x) + fabsf(dlx.f.x),
                         fabsf(dhx.f.y) + fabsf(dlx.f.y));
            F2 Dy = mkf2(fabsf(dhy.f.x) + fabsf(dly.f.x),
                         fabsf(dhy.f.y) + fabsf(dly.f.y));

            F2 bx = add2(fx, tw2x);          // qw + tw
            F2 by = add2(fy, tw2y);
            F2 ux = fma2(Dx, CM1, bx);       // 2*w (unclamped)
            F2 uy = fma2(Dy, CM1, by);
            F2 vx = add2(bx, Dx);            // 2*dx enclosing
            F2 vy = add2(by, Dy);

            F2 uxc = mkf2(fmaxf(ux.f.x, 0.0f), fmaxf(ux.f.y, 0.0f));
            F2 uyc = mkf2(fmaxf(uy.f.x, 0.0f), fmaxf(uy.f.y, 0.0f));

            F2 inter2 = mul2(uxc, uyc);          // 4*inter
            F2 sum4   = add2(qa4, ta4);          // 4*(qa+ta)
            F2 uni4   = fma2(inter2, CM1, sum4); // 4*uni
            F2 ac2    = mul2(vx, vy);            // 4*ac
            F2 prod2  = mul2(uni4, ac2);         // 16*uni*ac
            F2 r2     = mkf2(rcpa(prod2.f.x), rcpa(prod2.f.y));
            F2 iac2   = mul2(inter2, ac2);
            F2 S2     = fma2(uni4, uni4, iac2);  // 16*(inter*ac + uni^2)
            F2 mr2    = mul2(r2, CM2);           // -2/(16*uni*ac)

            // L1 cost pieces (pa/pb already hold 2-p)
            F2 ex = add2(dhx, dlx);              // 2*(qc - tc)
            F2 ey = add2(dhy, dly);
            float t0 = fmaf(fabsf(ex.f.x) + fabsf(ey.f.x), 2.5f,
                       fmaf(fabsf(fx.f.x) + fabsf(fy.f.x), 5.0f, pa[qi]));
            float t1 = fmaf(fabsf(ex.f.y) + fabsf(ey.f.y), 2.5f,
                       fmaf(fabsf(fx.f.y) + fabsf(fy.f.y), 5.0f, pb[qi]));

            F2 C2 = fma2(S2, mr2, mkf2(t0, t1));

            *reinterpret_cast<float2*>(opb + qi * NT + j0) = C2.f;
        }
    }
}

// ---------------------------------------------------------------------------
extern "C" void kernel_launch(void* const* d_in, const int* in_sizes, int n_in,
                              void* d_out, int out_size)
{
    const float* pred_logits = (const float*)d_in[0];
    const float* pred_boxes  = (const float*)d_in[1];
    const float* tgt_bbox    = (const float*)d_in[2];
    const int*   tgt_ids     = (const int*)d_in[3];
    float* out = (float*)d_out;

    fused_cost_kernel<<<NR / TQ, 160>>>(pred_logits, pred_boxes,
                                        tgt_bbox, tgt_ids, out);
}